// round 8
// baseline (speedup 1.0000x reference)
#include <cuda_runtime.h>
#include <cuda_fp16.h>
#include <mma.h>
using namespace nvcuda;

#define N_NODES 100000
#define E_EDGES 1600000
#define DIM     128
#define HC      50          // H*C
#define HCW     56          // fp16 row length (7 x uint4 = 112B, 16B aligned rows)
#define NHEADS  5
#define NGRAPH  256
#define NEG_SLOPE 0.2f
#define NCHUNK  1024
#define NBLK_SCAN ((N_NODES + NCHUNK - 1) / NCHUNK)   // 98

// ---------------- scratch ----------------------------------------------------
__device__ __align__(16) __half g_xwh [N_NODES * HCW];  // fp16 projected feats
__device__ __align__(16) float g_asrc [N_NODES * 8];
__device__ __align__(16) float g_adst [N_NODES * 8];
__device__ __align__(16) float g_gsum [NGRAPH * HCW];
__device__ __align__(16) float g_cnt  [NGRAPH];
__device__ int g_deg   [N_NODES];
__device__ int g_start [N_NODES];
__device__ int g_pos   [N_NODES];
__device__ int g_csrc  [E_EDGES];
// lookback scan state
__device__ volatile int g_aggr2[128];
__device__ volatile int g_incl2[128];
__device__ volatile int g_stat2[128];   // 0 none, 1 aggregate, 2 inclusive

// ---------------- reductions -------------------------------------------------
__device__ __forceinline__ void red4(float* p, float a, float b, float c, float d) {
    asm volatile("red.global.add.v4.f32 [%0], {%1,%2,%3,%4};"
                 :: "l"(p), "f"(a), "f"(b), "f"(c), "f"(d) : "memory");
}
__device__ __forceinline__ void red1(float* p, float a) {
    asm volatile("red.global.add.f32 [%0], %1;" :: "l"(p), "f"(a) : "memory");
}

// ---------------- K0: init ---------------------------------------------------
__global__ void k_init() {
    int i = blockIdx.x * blockDim.x + threadIdx.x;
    int stride = gridDim.x * blockDim.x;
    for (int j = i; j < N_NODES; j += stride) g_deg[j] = 0;
    for (int j = i; j < NGRAPH * HCW; j += stride) g_gsum[j] = 0.f;
    for (int j = i; j < NGRAPH; j += stride) g_cnt[j] = 0.f;
    if (i < 128) g_stat2[i] = 0;
}

// ---------------- K1: wmma GEMM + attention dots + fp16 store ----------------
__global__ __launch_bounds__(128) void k_gemm(const float* __restrict__ x,
                                              const float* __restrict__ W,
                                              const float* __restrict__ att_src,
                                              const float* __restrict__ att_dst) {
    __shared__ __half xs[32 * 136];
    __shared__ __half ws[128 * 64];
    __shared__ float  cs[32 * 68];
    __shared__ float  s_as[HC], s_ad[HC];

    int t = threadIdx.x, warp = t >> 5;
    int n0 = blockIdx.x * 32;

    if (t < HC) { s_as[t] = att_src[t]; s_ad[t] = att_dst[t]; }

    const float4* xg = (const float4*)(x + (size_t)n0 * DIM);
    for (int i = t; i < 32 * 32; i += 128) {
        int r = i >> 5, c4 = i & 31;
        float4 v = xg[r * 32 + c4];
        __half* p = &xs[r * 136 + c4 * 4];
        p[0] = __float2half(v.x); p[1] = __float2half(v.y);
        p[2] = __float2half(v.z); p[3] = __float2half(v.w);
    }
    for (int i = t; i < 128 * 64; i += 128) {
        int r = i >> 6, c = i & 63;
        ws[i] = __float2half(c < HC ? W[r * HC + c] : 0.f);
    }
    __syncthreads();

#pragma unroll
    for (int mt = 0; mt < 2; mt++) {
        wmma::fragment<wmma::accumulator, 16, 16, 16, float> cfrag;
        wmma::fill_fragment(cfrag, 0.f);
#pragma unroll
        for (int k = 0; k < 8; k++) {
            wmma::fragment<wmma::matrix_a, 16, 16, 16, __half, wmma::row_major> a;
            wmma::fragment<wmma::matrix_b, 16, 16, 16, __half, wmma::row_major> b;
            wmma::load_matrix_sync(a, xs + mt * 16 * 136 + k * 16, 136);
            wmma::load_matrix_sync(b, ws + k * 16 * 64 + warp * 16, 64);
            wmma::mma_sync(cfrag, a, b, cfrag);
        }
        wmma::store_matrix_sync(cs + mt * 16 * 68 + warp * 16, cfrag, 68,
                                wmma::mem_row_major);
    }
    __syncthreads();

    // fp16 store of xw (56 cols, pads zero)
    for (int i = t; i < 32 * 28; i += 128) {
        int n = i / 28, c2 = i - n * 28;
        float lo = (2 * c2     < HC) ? cs[n * 68 + 2 * c2]     : 0.f;
        float hi = (2 * c2 + 1 < HC) ? cs[n * 68 + 2 * c2 + 1] : 0.f;
        *(__half2*)(g_xwh + (size_t)(n0 + n) * HCW + 2 * c2) = __floats2half2_rn(lo, hi);
    }

    // attention dots: 160 jobs (32 nodes x 5 heads)
    for (int j = t; j < 160; j += 128) {
        int n = j / 5, h = j - 5 * n;
        const float* row = &cs[n * 68 + h * 10];
        float a = 0.f, d = 0.f;
#pragma unroll
        for (int c = 0; c < 10; c++) {
            a += row[c] * s_as[h * 10 + c];
            d += row[c] * s_ad[h * 10 + c];
        }
        g_asrc[(n0 + n) * 8 + h] = a;
        g_adst[(n0 + n) * 8 + h] = d;
    }
}

// ---------------- K2: degree count (int4, 4 edges/thread) --------------------
__global__ void k_count(const int* __restrict__ ei) {
    int t = blockIdx.x * blockDim.x + threadIdx.x;
    if (t >= E_EDGES / 4) return;
    int4 d = __ldg((const int4*)(ei + E_EDGES) + t);
    atomicAdd(&g_deg[d.x], 1);
    atomicAdd(&g_deg[d.y], 1);
    atomicAdd(&g_deg[d.z], 1);
    atomicAdd(&g_deg[d.w], 1);
}

// ---------------- K3: single-kernel decoupled-lookback scan ------------------
__global__ __launch_bounds__(NCHUNK) void k_scan() {
    __shared__ int s[NCHUNK];
    __shared__ int s_prefix;
    int tid = threadIdx.x, b = blockIdx.x;
    int i = b * NCHUNK + tid;
    int v = (i < N_NODES) ? g_deg[i] : 0;
    s[tid] = v;
    __syncthreads();
    for (int off = 1; off < NCHUNK; off <<= 1) {
        int tv = (tid >= off) ? s[tid - off] : 0;
        __syncthreads();
        s[tid] += tv;
        __syncthreads();
    }
    int total = s[NCHUNK - 1];

    if (tid == 0) {
        if (b == 0) {
            g_incl2[0] = total; __threadfence(); g_stat2[0] = 2;
            s_prefix = 0;
        } else {
            g_aggr2[b] = total; __threadfence(); g_stat2[b] = 1;
            int pref = 0, j = b - 1;
            while (j >= 0) {
                int st;
                do { st = g_stat2[j]; } while (st == 0);
                __threadfence();
                if (st == 2) { pref += g_incl2[j]; break; }
                pref += g_aggr2[j]; --j;
            }
            g_incl2[b] = pref + total; __threadfence(); g_stat2[b] = 2;
            s_prefix = pref;
        }
    }
    __syncthreads();
    if (i < N_NODES) {
        int st = s_prefix + s[tid] - v;     // exclusive
        g_start[i] = st;
        g_pos[i]   = st;
    }
}

// ---------------- K4: fill CSR (int4, 4 edges/thread) ------------------------
__global__ void k_fill(const int* __restrict__ ei) {
    int t = blockIdx.x * blockDim.x + threadIdx.x;
    if (t >= E_EDGES / 4) return;
    int4 s4 = __ldg((const int4*)ei + t);
    int4 d4 = __ldg((const int4*)(ei + E_EDGES) + t);
    g_csrc[atomicAdd(&g_pos[d4.x], 1)] = s4.x;
    g_csrc[atomicAdd(&g_pos[d4.y], 1)] = s4.y;
    g_csrc[atomicAdd(&g_pos[d4.z], 1)] = s4.z;
    g_csrc[atomicAdd(&g_pos[d4.w], 1)] = s4.w;
}

// ---------------- K5: gather SpMM, 8-lane groups, 64 nodes/block -------------
__device__ __forceinline__ float eluf(float v) { return v > 0.f ? v : expm1f(v); }

__global__ __launch_bounds__(512) void k_spmm(const float* __restrict__ bias,
                                              const int* __restrict__ batch) {
    __shared__ float4 red[64][14];      // 64 nodes x 14 float4 (56 floats)
    __shared__ float  sb[HCW];
    __shared__ int    sgf, sgl, svalid;

    int tid = threadIdx.x;
    int grp = tid >> 3;                 // 0..63 node slot
    int lane = tid & 7;
    int n0 = blockIdx.x * 64;
    int n = n0 + grp;
    bool valid = n < N_NODES;
    int nc = valid ? n : N_NODES - 1;

    if (tid < HC) sb[tid] = bias[tid];
    else if (tid < HCW) sb[tid] = 0.f;
    if (tid == 0) { sgf = __ldg(batch + n0); svalid = min(64, N_NODES - n0); }
    if (tid == 1) sgl = __ldg(batch + min(n0 + 63, N_NODES - 1));

    int g = __ldg(batch + nc);
    int start = g_start[nc];
    int deg = valid ? g_deg[nc] : -1;   // -1: loop body never runs

    int c0 = 8 * lane;                  // channel base (lane 7: none)
    int hlo = min(c0, HC - 1) / 10;
    int hhi = min(c0 + 7, HC - 1) / 10;
    bool sel1 = (min(c0 + 1, HC - 1) / 10) == hlo;
    bool sel2 = (min(c0 + 2, HC - 1) / 10) == hlo;
    bool sel3 = (min(c0 + 3, HC - 1) / 10) == hlo;
    bool sel4 = (min(c0 + 4, HC - 1) / 10) == hlo;
    bool sel5 = (min(c0 + 5, HC - 1) / 10) == hlo;
    bool sel6 = (min(c0 + 6, HC - 1) / 10) == hlo;
    bool sel7 = (min(c0 + 7, HC - 1) / 10) == hlo;

    unsigned gm = 0xFFu << (tid & 24);  // 8-lane group mask (warp-local)

    float adv = 0.f;
    if (lane < NHEADS) adv = __ldg(g_adst + nc * 8 + lane);

    float2 a0 = {0.f,0.f}, a1 = {0.f,0.f}, a2 = {0.f,0.f}, a3 = {0.f,0.f};
    float den = 0.f;

    int end = start + deg;
    int s_next = nc;                    // self-loop first
    for (int i = start; i <= end; ++i) {
        int s = s_next;
        if (i < end) s_next = __ldg(g_csrc + i);

        float w = 0.f;
        if (lane < NHEADS) {
            float l = __ldg(g_asrc + s * 8 + lane) + adv;
            l = l > 0.f ? l : NEG_SLOPE * l;
            w = __expf(l);
            den += w;
        }
        float wlo = __shfl_sync(gm, w, hlo, 8);
        float whi = __shfl_sync(gm, w, hhi, 8);

        if (lane < 7) {
            uint4 u = __ldg((const uint4*)(g_xwh + (size_t)s * HCW + c0));
            float2 f0 = __half22float2(*(__half2*)&u.x);
            float2 f1 = __half22float2(*(__half2*)&u.y);
            float2 f2 = __half22float2(*(__half2*)&u.z);
            float2 f3 = __half22float2(*(__half2*)&u.w);
            a0.x += wlo * f0.x;
            a0.y += (sel1 ? wlo : whi) * f0.y;
            a1.x += (sel2 ? wlo : whi) * f1.x;
            a1.y += (sel3 ? wlo : whi) * f1.y;
            a2.x += (sel4 ? wlo : whi) * f2.x;
            a2.y += (sel5 ? wlo : whi) * f2.y;
            a3.x += (sel6 ? wlo : whi) * f3.x;
            a3.y += (sel7 ? wlo : whi) * f3.y;
        }
    }

    float invd = (lane < NHEADS) ? (1.f / den) : 0.f;
    float ilo = __shfl_sync(gm, invd, hlo, 8);
    float ihi = __shfl_sync(gm, invd, hhi, 8);

    __syncthreads();                    // sb/sgf/sgl ready

    float4 o03 = make_float4(0.f, 0.f, 0.f, 0.f);
    float4 o47 = make_float4(0.f, 0.f, 0.f, 0.f);
    if (valid && lane < 7) {
        o03.x = (c0 + 0 < HC) ? eluf(a0.x * ilo + sb[c0 + 0]) : 0.f;
        o03.y = (c0 + 1 < HC) ? eluf(a0.y * (sel1 ? ilo : ihi) + sb[c0 + 1]) : 0.f;
        o03.z = (c0 + 2 < HC) ? eluf(a1.x * (sel2 ? ilo : ihi) + sb[c0 + 2]) : 0.f;
        o03.w = (c0 + 3 < HC) ? eluf(a1.y * (sel3 ? ilo : ihi) + sb[c0 + 3]) : 0.f;
        o47.x = (c0 + 4 < HC) ? eluf(a2.x * (sel4 ? ilo : ihi) + sb[c0 + 4]) : 0.f;
        o47.y = (c0 + 5 < HC) ? eluf(a2.y * (sel5 ? ilo : ihi) + sb[c0 + 5]) : 0.f;
        o47.z = (c0 + 6 < HC) ? eluf(a3.x * (sel6 ? ilo : ihi) + sb[c0 + 6]) : 0.f;
        o47.w = (c0 + 7 < HC) ? eluf(a3.y * (sel7 ? ilo : ihi) + sb[c0 + 7]) : 0.f;
    }

    if (sgf == sgl) {
        if (lane < 7) { red[grp][2 * lane] = o03; red[grp][2 * lane + 1] = o47; }
        __syncthreads();
#pragma unroll
        for (int sft = 32; sft > 0; sft >>= 1) {
            if (grp < sft && lane < 7) {
                float4 x0 = red[grp][2 * lane],     y0 = red[grp + sft][2 * lane];
                float4 x1 = red[grp][2 * lane + 1], y1 = red[grp + sft][2 * lane + 1];
                x0.x += y0.x; x0.y += y0.y; x0.z += y0.z; x0.w += y0.w;
                x1.x += y1.x; x1.y += y1.y; x1.z += y1.z; x1.w += y1.w;
                red[grp][2 * lane] = x0; red[grp][2 * lane + 1] = x1;
            }
            __syncthreads();
        }
        if (grp == 0 && lane < 7) {
            float4 r0 = red[0][2 * lane], r1 = red[0][2 * lane + 1];
            red4(&g_gsum[sgf * HCW + c0],     r0.x, r0.y, r0.z, r0.w);
            red4(&g_gsum[sgf * HCW + c0 + 4], r1.x, r1.y, r1.z, r1.w);
        }
        if (tid == 0) red1(&g_cnt[sgf], (float)svalid);
    } else {
        if (valid && lane < 7) {
            red4(&g_gsum[g * HCW + c0],     o03.x, o03.y, o03.z, o03.w);
            red4(&g_gsum[g * HCW + c0 + 4], o47.x, o47.y, o47.z, o47.w);
        }
        if (valid && lane == 0) red1(&g_cnt[g], 1.f);
    }
}

// ---------------- K6: final linear + sigmoid --------------------------------
__global__ void k_final(const float* __restrict__ lin_w,
                        const float* __restrict__ lin_b,
                        float* __restrict__ out, int out_size) {
    int g = threadIdx.x;
    float cnt = g_cnt[g];
    float inv = 1.f / fmaxf(cnt, 1.f);
    float dot = 0.f;
#pragma unroll
    for (int c = 0; c < HC; c++) {
        float h = g_gsum[g * HCW + c] * inv;
        int idx = g * HC + c;
        if (idx < out_size) out[idx] = h;
        dot += h * __ldg(lin_w + c);
    }
    float y = 1.f / (1.f + __expf(-(dot + __ldg(lin_b))));
    int yidx = NGRAPH * HC + g;
    if (yidx < out_size) out[yidx] = y;
}

// ---------------- launch -----------------------------------------------------
extern "C" void kernel_launch(void* const* d_in, const int* in_sizes, int n_in,
                              void* d_out, int out_size) {
    const float* x       = (const float*)d_in[0];
    const float* W       = (const float*)d_in[1];
    const float* att_src = (const float*)d_in[2];
    const float* att_dst = (const float*)d_in[3];
    const float* bias    = (const float*)d_in[4];
    const float* lin_w   = (const float*)d_in[5];
    const float* lin_b   = (const float*)d_in[6];
    const int*   ei      = (const int*)d_in[7];
    const int*   batch   = (const int*)d_in[8];
    float*       out     = (float*)d_out;

    k_init <<<256, 256>>>();
    k_count<<<(E_EDGES / 4 + 255) / 256, 256>>>(ei);
    k_gemm <<<N_NODES / 32, 128>>>(x, W, att_src, att_dst);
    k_scan <<<NBLK_SCAN, NCHUNK>>>();
    k_fill <<<(E_EDGES / 4 + 255) / 256, 256>>>(ei);
    k_spmm <<<(N_NODES + 63) / 64, 512>>>(bias, batch);
    k_final<<<1, 256>>>(lin_w, lin_b, out, out_size);
}

// round 9
// speedup vs baseline: 1.0034x; 1.0034x over previous
#include <cuda_runtime.h>
#include <cuda_fp16.h>
#include <mma.h>
using namespace nvcuda;

#define N_NODES 100000
#define E_EDGES 1600000
#define DIM     128
#define HC      50          // H*C
#define HCW     56          // fp16 row length (7 x uint4 = 112B, 16B aligned rows)
#define NHEADS  5
#define NGRAPH  256
#define NEG_SLOPE 0.2f
#define NCHUNK  1024
#define NBLK_SCAN ((N_NODES + NCHUNK - 1) / NCHUNK)   // 98

// ---------------- scratch ----------------------------------------------------
__device__ __align__(16) __half g_xwh [N_NODES * HCW];  // fp16 projected feats
__device__ __align__(16) float g_asrc [N_NODES * 8];
__device__ __align__(16) float g_adst [N_NODES * 8];
__device__ __align__(16) float g_gsum [NGRAPH * HCW];
__device__ __align__(16) float g_cnt  [NGRAPH];
__device__ int g_deg   [N_NODES];
__device__ int g_start [N_NODES];
__device__ int g_pos   [N_NODES];
__device__ int g_csrc  [E_EDGES];
// lookback scan state
__device__ volatile int g_aggr2[128];
__device__ volatile int g_incl2[128];
__device__ volatile int g_stat2[128];   // 0 none, 1 aggregate, 2 inclusive

// ---------------- reductions -------------------------------------------------
__device__ __forceinline__ void red4(float* p, float a, float b, float c, float d) {
    asm volatile("red.global.add.v4.f32 [%0], {%1,%2,%3,%4};"
                 :: "l"(p), "f"(a), "f"(b), "f"(c), "f"(d) : "memory");
}
__device__ __forceinline__ void red1(float* p, float a) {
    asm volatile("red.global.add.f32 [%0], %1;" :: "l"(p), "f"(a) : "memory");
}

// ---------------- K0: init ---------------------------------------------------
__global__ void k_init() {
    int i = blockIdx.x * blockDim.x + threadIdx.x;
    int stride = gridDim.x * blockDim.x;
    for (int j = i; j < N_NODES; j += stride) g_deg[j] = 0;
    for (int j = i; j < NGRAPH * HCW; j += stride) g_gsum[j] = 0.f;
    for (int j = i; j < NGRAPH; j += stride) g_cnt[j] = 0.f;
    if (i < 128) g_stat2[i] = 0;
}

// ---------------- K1: wmma GEMM + attention dots + fp16 store ----------------
__global__ __launch_bounds__(128) void k_gemm(const float* __restrict__ x,
                                              const float* __restrict__ W,
                                              const float* __restrict__ att_src,
                                              const float* __restrict__ att_dst) {
    __shared__ __half xs[32 * 136];
    __shared__ __half ws[128 * 64];
    __shared__ float  cs[32 * 68];
    __shared__ float  s_as[HC], s_ad[HC];

    int t = threadIdx.x, warp = t >> 5;
    int n0 = blockIdx.x * 32;

    if (t < HC) { s_as[t] = att_src[t]; s_ad[t] = att_dst[t]; }

    const float4* xg = (const float4*)(x + (size_t)n0 * DIM);
    for (int i = t; i < 32 * 32; i += 128) {
        int r = i >> 5, c4 = i & 31;
        float4 v = xg[r * 32 + c4];
        __half* p = &xs[r * 136 + c4 * 4];
        p[0] = __float2half(v.x); p[1] = __float2half(v.y);
        p[2] = __float2half(v.z); p[3] = __float2half(v.w);
    }
    for (int i = t; i < 128 * 64; i += 128) {
        int r = i >> 6, c = i & 63;
        ws[i] = __float2half(c < HC ? W[r * HC + c] : 0.f);
    }
    __syncthreads();

#pragma unroll
    for (int mt = 0; mt < 2; mt++) {
        wmma::fragment<wmma::accumulator, 16, 16, 16, float> cfrag;
        wmma::fill_fragment(cfrag, 0.f);
#pragma unroll
        for (int k = 0; k < 8; k++) {
            wmma::fragment<wmma::matrix_a, 16, 16, 16, __half, wmma::row_major> a;
            wmma::fragment<wmma::matrix_b, 16, 16, 16, __half, wmma::row_major> b;
            wmma::load_matrix_sync(a, xs + mt * 16 * 136 + k * 16, 136);
            wmma::load_matrix_sync(b, ws + k * 16 * 64 + warp * 16, 64);
            wmma::mma_sync(cfrag, a, b, cfrag);
        }
        wmma::store_matrix_sync(cs + mt * 16 * 68 + warp * 16, cfrag, 68,
                                wmma::mem_row_major);
    }
    __syncthreads();

    // fp16 store of xw (56 cols, pads zero)
    for (int i = t; i < 32 * 28; i += 128) {
        int n = i / 28, c2 = i - n * 28;
        float lo = (2 * c2     < HC) ? cs[n * 68 + 2 * c2]     : 0.f;
        float hi = (2 * c2 + 1 < HC) ? cs[n * 68 + 2 * c2 + 1] : 0.f;
        *(__half2*)(g_xwh + (size_t)(n0 + n) * HCW + 2 * c2) = __floats2half2_rn(lo, hi);
    }

    // attention dots: 160 jobs (32 nodes x 5 heads)
    for (int j = t; j < 160; j += 128) {
        int n = j / 5, h = j - 5 * n;
        const float* row = &cs[n * 68 + h * 10];
        float a = 0.f, d = 0.f;
#pragma unroll
        for (int c = 0; c < 10; c++) {
            a += row[c] * s_as[h * 10 + c];
            d += row[c] * s_ad[h * 10 + c];
        }
        g_asrc[(n0 + n) * 8 + h] = a;
        g_adst[(n0 + n) * 8 + h] = d;
    }
}

// ---------------- K2: degree count (int4, 4 edges/thread) --------------------
__global__ void k_count(const int* __restrict__ ei) {
    int t = blockIdx.x * blockDim.x + threadIdx.x;
    if (t >= E_EDGES / 4) return;
    int4 d = __ldg((const int4*)(ei + E_EDGES) + t);
    atomicAdd(&g_deg[d.x], 1);
    atomicAdd(&g_deg[d.y], 1);
    atomicAdd(&g_deg[d.z], 1);
    atomicAdd(&g_deg[d.w], 1);
}

// ---------------- K3: single-kernel decoupled-lookback scan ------------------
__global__ __launch_bounds__(NCHUNK) void k_scan() {
    __shared__ int s[NCHUNK];
    __shared__ int s_prefix;
    int tid = threadIdx.x, b = blockIdx.x;
    int i = b * NCHUNK + tid;
    int v = (i < N_NODES) ? g_deg[i] : 0;
    s[tid] = v;
    __syncthreads();
    for (int off = 1; off < NCHUNK; off <<= 1) {
        int tv = (tid >= off) ? s[tid - off] : 0;
        __syncthreads();
        s[tid] += tv;
        __syncthreads();
    }
    int total = s[NCHUNK - 1];

    if (tid == 0) {
        if (b == 0) {
            g_incl2[0] = total; __threadfence(); g_stat2[0] = 2;
            s_prefix = 0;
        } else {
            g_aggr2[b] = total; __threadfence(); g_stat2[b] = 1;
            int pref = 0, j = b - 1;
            while (j >= 0) {
                int st;
                do { st = g_stat2[j]; } while (st == 0);
                __threadfence();
                if (st == 2) { pref += g_incl2[j]; break; }
                pref += g_aggr2[j]; --j;
            }
            g_incl2[b] = pref + total; __threadfence(); g_stat2[b] = 2;
            s_prefix = pref;
        }
    }
    __syncthreads();
    if (i < N_NODES) {
        int st = s_prefix + s[tid] - v;     // exclusive
        g_start[i] = st;
        g_pos[i]   = st;
    }
}

// ---------------- K4: fill CSR (int4, 4 edges/thread) ------------------------
__global__ void k_fill(const int* __restrict__ ei) {
    int t = blockIdx.x * blockDim.x + threadIdx.x;
    if (t >= E_EDGES / 4) return;
    int4 s4 = __ldg((const int4*)ei + t);
    int4 d4 = __ldg((const int4*)(ei + E_EDGES) + t);
    g_csrc[atomicAdd(&g_pos[d4.x], 1)] = s4.x;
    g_csrc[atomicAdd(&g_pos[d4.y], 1)] = s4.y;
    g_csrc[atomicAdd(&g_pos[d4.z], 1)] = s4.z;
    g_csrc[atomicAdd(&g_pos[d4.w], 1)] = s4.w;
}

// ---------------- K5: gather SpMM, 8-lane groups, 64 nodes/block -------------
__device__ __forceinline__ float eluf(float v) { return v > 0.f ? v : expm1f(v); }

__global__ __launch_bounds__(512) void k_spmm(const float* __restrict__ bias,
                                              const int* __restrict__ batch) {
    __shared__ float4 red[64][14];      // 64 nodes x 14 float4 (56 floats)
    __shared__ float  sb[HCW];
    __shared__ int    sgf, sgl, svalid;

    int tid = threadIdx.x;
    int grp = tid >> 3;                 // 0..63 node slot
    int lane = tid & 7;
    int n0 = blockIdx.x * 64;
    int n = n0 + grp;
    bool valid = n < N_NODES;
    int nc = valid ? n : N_NODES - 1;

    if (tid < HC) sb[tid] = bias[tid];
    else if (tid < HCW) sb[tid] = 0.f;
    if (tid == 0) { sgf = __ldg(batch + n0); svalid = min(64, N_NODES - n0); }
    if (tid == 1) sgl = __ldg(batch + min(n0 + 63, N_NODES - 1));

    int g = __ldg(batch + nc);
    int start = g_start[nc];
    int deg = valid ? g_deg[nc] : -1;   // -1: loop body never runs

    int c0 = 8 * lane;                  // channel base (lane 7: none)
    int hlo = min(c0, HC - 1) / 10;
    int hhi = min(c0 + 7, HC - 1) / 10;
    bool sel1 = (min(c0 + 1, HC - 1) / 10) == hlo;
    bool sel2 = (min(c0 + 2, HC - 1) / 10) == hlo;
    bool sel3 = (min(c0 + 3, HC - 1) / 10) == hlo;
    bool sel4 = (min(c0 + 4, HC - 1) / 10) == hlo;
    bool sel5 = (min(c0 + 5, HC - 1) / 10) == hlo;
    bool sel6 = (min(c0 + 6, HC - 1) / 10) == hlo;
    bool sel7 = (min(c0 + 7, HC - 1) / 10) == hlo;

    unsigned gm = 0xFFu << (tid & 24);  // 8-lane group mask (warp-local)

    float adv = 0.f;
    if (lane < NHEADS) adv = __ldg(g_adst + nc * 8 + lane);

    float2 a0 = {0.f,0.f}, a1 = {0.f,0.f}, a2 = {0.f,0.f}, a3 = {0.f,0.f};
    float den = 0.f;

    int end = start + deg;
    int s_next = nc;                    // self-loop first
    for (int i = start; i <= end; ++i) {
        int s = s_next;
        if (i < end) s_next = __ldg(g_csrc + i);

        float w = 0.f;
        if (lane < NHEADS) {
            float l = __ldg(g_asrc + s * 8 + lane) + adv;
            l = l > 0.f ? l : NEG_SLOPE * l;
            w = __expf(l);
            den += w;
        }
        float wlo = __shfl_sync(gm, w, hlo, 8);
        float whi = __shfl_sync(gm, w, hhi, 8);

        if (lane < 7) {
            uint4 u = __ldg((const uint4*)(g_xwh + (size_t)s * HCW + c0));
            float2 f0 = __half22float2(*(__half2*)&u.x);
            float2 f1 = __half22float2(*(__half2*)&u.y);
            float2 f2 = __half22float2(*(__half2*)&u.z);
            float2 f3 = __half22float2(*(__half2*)&u.w);
            a0.x += wlo * f0.x;
            a0.y += (sel1 ? wlo : whi) * f0.y;
            a1.x += (sel2 ? wlo : whi) * f1.x;
            a1.y += (sel3 ? wlo : whi) * f1.y;
            a2.x += (sel4 ? wlo : whi) * f2.x;
            a2.y += (sel5 ? wlo : whi) * f2.y;
            a3.x += (sel6 ? wlo : whi) * f3.x;
            a3.y += (sel7 ? wlo : whi) * f3.y;
        }
    }

    float invd = (lane < NHEADS) ? (1.f / den) : 0.f;
    float ilo = __shfl_sync(gm, invd, hlo, 8);
    float ihi = __shfl_sync(gm, invd, hhi, 8);

    __syncthreads();                    // sb/sgf/sgl ready

    float4 o03 = make_float4(0.f, 0.f, 0.f, 0.f);
    float4 o47 = make_float4(0.f, 0.f, 0.f, 0.f);
    if (valid && lane < 7) {
        o03.x = (c0 + 0 < HC) ? eluf(a0.x * ilo + sb[c0 + 0]) : 0.f;
        o03.y = (c0 + 1 < HC) ? eluf(a0.y * (sel1 ? ilo : ihi) + sb[c0 + 1]) : 0.f;
        o03.z = (c0 + 2 < HC) ? eluf(a1.x * (sel2 ? ilo : ihi) + sb[c0 + 2]) : 0.f;
        o03.w = (c0 + 3 < HC) ? eluf(a1.y * (sel3 ? ilo : ihi) + sb[c0 + 3]) : 0.f;
        o47.x = (c0 + 4 < HC) ? eluf(a2.x * (sel4 ? ilo : ihi) + sb[c0 + 4]) : 0.f;
        o47.y = (c0 + 5 < HC) ? eluf(a2.y * (sel5 ? ilo : ihi) + sb[c0 + 5]) : 0.f;
        o47.z = (c0 + 6 < HC) ? eluf(a3.x * (sel6 ? ilo : ihi) + sb[c0 + 6]) : 0.f;
        o47.w = (c0 + 7 < HC) ? eluf(a3.y * (sel7 ? ilo : ihi) + sb[c0 + 7]) : 0.f;
    }

    if (sgf == sgl) {
        if (lane < 7) { red[grp][2 * lane] = o03; red[grp][2 * lane + 1] = o47; }
        __syncthreads();
#pragma unroll
        for (int sft = 32; sft > 0; sft >>= 1) {
            if (grp < sft && lane < 7) {
                float4 x0 = red[grp][2 * lane],     y0 = red[grp + sft][2 * lane];
                float4 x1 = red[grp][2 * lane + 1], y1 = red[grp + sft][2 * lane + 1];
                x0.x += y0.x; x0.y += y0.y; x0.z += y0.z; x0.w += y0.w;
                x1.x += y1.x; x1.y += y1.y; x1.z += y1.z; x1.w += y1.w;
                red[grp][2 * lane] = x0; red[grp][2 * lane + 1] = x1;
            }
            __syncthreads();
        }
        if (grp == 0 && lane < 7) {
            float4 r0 = red[0][2 * lane], r1 = red[0][2 * lane + 1];
            red4(&g_gsum[sgf * HCW + c0],     r0.x, r0.y, r0.z, r0.w);
            red4(&g_gsum[sgf * HCW + c0 + 4], r1.x, r1.y, r1.z, r1.w);
        }
        if (tid == 0) red1(&g_cnt[sgf], (float)svalid);
    } else {
        if (valid && lane < 7) {
            red4(&g_gsum[g * HCW + c0],     o03.x, o03.y, o03.z, o03.w);
            red4(&g_gsum[g * HCW + c0 + 4], o47.x, o47.y, o47.z, o47.w);
        }
        if (valid && lane == 0) red1(&g_cnt[g], 1.f);
    }
}

// ---------------- K6: final linear + sigmoid --------------------------------
__global__ void k_final(const float* __restrict__ lin_w,
                        const float* __restrict__ lin_b,
                        float* __restrict__ out, int out_size) {
    int g = threadIdx.x;
    float cnt = g_cnt[g];
    float inv = 1.f / fmaxf(cnt, 1.f);
    float dot = 0.f;
#pragma unroll
    for (int c = 0; c < HC; c++) {
        float h = g_gsum[g * HCW + c] * inv;
        int idx = g * HC + c;
        if (idx < out_size) out[idx] = h;
        dot += h * __ldg(lin_w + c);
    }
    float y = 1.f / (1.f + __expf(-(dot + __ldg(lin_b))));
    int yidx = NGRAPH * HC + g;
    if (yidx < out_size) out[yidx] = y;
}

// ---------------- launch -----------------------------------------------------
extern "C" void kernel_launch(void* const* d_in, const int* in_sizes, int n_in,
                              void* d_out, int out_size) {
    const float* x       = (const float*)d_in[0];
    const float* W       = (const float*)d_in[1];
    const float* att_src = (const float*)d_in[2];
    const float* att_dst = (const float*)d_in[3];
    const float* bias    = (const float*)d_in[4];
    const float* lin_w   = (const float*)d_in[5];
    const float* lin_b   = (const float*)d_in[6];
    const int*   ei      = (const int*)d_in[7];
    const int*   batch   = (const int*)d_in[8];
    float*       out     = (float*)d_out;

    k_init <<<256, 256>>>();
    k_count<<<(E_EDGES / 4 + 255) / 256, 256>>>(ei);
    k_gemm <<<N_NODES / 32, 128>>>(x, W, att_src, att_dst);
    k_scan <<<NBLK_SCAN, NCHUNK>>>();
    k_fill <<<(E_EDGES / 4 + 255) / 256, 256>>>(ei);
    k_spmm <<<(N_NODES + 63) / 64, 512>>>(bias, batch);
    k_final<<<1, 256>>>(lin_w, lin_b, out, out_size);
}

// round 10
// speedup vs baseline: 1.1258x; 1.1220x over previous
#include <cuda_runtime.h>
#include <cuda_fp16.h>
#include <mma.h>
using namespace nvcuda;

#define N_NODES 100000
#define E_EDGES 1600000
#define DIM     128
#define HC      50          // H*C
#define HCW     52          // fp16 row length (26 half2, 13 x 8B)
#define NHEADS  5
#define NGRAPH  256
#define NEG_SLOPE 0.2f
#define NCHUNK  1024
#define NBLK_SCAN ((N_NODES + NCHUNK - 1) / NCHUNK)   // 98

// ---------------- scratch ----------------------------------------------------
__device__ __align__(16) __half g_xwh [N_NODES * HCW];  // fp16 projected feats
__device__ __align__(16) float g_asrc [N_NODES * 8];
__device__ __align__(16) float g_adst [N_NODES * 8];
__device__ __align__(16) float g_gsum [NGRAPH * HCW];
__device__ __align__(16) float g_cnt  [NGRAPH];
__device__ int g_deg   [N_NODES];
__device__ int g_offl  [N_NODES];
__device__ int g_bpre  [128];
__device__ int g_bsum  [128];
__device__ int g_start [N_NODES];
__device__ int g_pos   [N_NODES];
__device__ int g_csrc  [E_EDGES];

// ---------------- reductions -------------------------------------------------
__device__ __forceinline__ void red4(float* p, float a, float b, float c, float d) {
    asm volatile("red.global.add.v4.f32 [%0], {%1,%2,%3,%4};"
                 :: "l"(p), "f"(a), "f"(b), "f"(c), "f"(d) : "memory");
}
__device__ __forceinline__ void red1(float* p, float a) {
    asm volatile("red.global.add.f32 [%0], %1;" :: "l"(p), "f"(a) : "memory");
}

// ---------------- K0: init ---------------------------------------------------
__global__ void k_init() {
    int i = blockIdx.x * blockDim.x + threadIdx.x;
    int stride = gridDim.x * blockDim.x;
    for (int j = i; j < N_NODES; j += stride) g_deg[j] = 0;
    for (int j = i; j < NGRAPH * HCW; j += stride) g_gsum[j] = 0.f;
    for (int j = i; j < NGRAPH; j += stride) g_cnt[j] = 0.f;
}

// ---------------- K1: wmma GEMM + attention dots + fp16 store ----------------
__global__ __launch_bounds__(128) void k_gemm(const float* __restrict__ x,
                                              const float* __restrict__ W,
                                              const float* __restrict__ att_src,
                                              const float* __restrict__ att_dst) {
    __shared__ __half xs[32 * 136];
    __shared__ __half ws[128 * 64];
    __shared__ float  cs[32 * 68];
    __shared__ float  s_as[HC], s_ad[HC];

    int t = threadIdx.x, warp = t >> 5;
    int n0 = blockIdx.x * 32;

    if (t < HC) { s_as[t] = att_src[t]; s_ad[t] = att_dst[t]; }

    const float4* xg = (const float4*)(x + (size_t)n0 * DIM);
    for (int i = t; i < 32 * 32; i += 128) {
        int r = i >> 5, c4 = i & 31;
        float4 v = xg[r * 32 + c4];
        __half* p = &xs[r * 136 + c4 * 4];
        p[0] = __float2half(v.x); p[1] = __float2half(v.y);
        p[2] = __float2half(v.z); p[3] = __float2half(v.w);
    }
    for (int i = t; i < 128 * 64; i += 128) {
        int r = i >> 6, c = i & 63;
        ws[i] = __float2half(c < HC ? W[r * HC + c] : 0.f);
    }
    __syncthreads();

#pragma unroll
    for (int mt = 0; mt < 2; mt++) {
        wmma::fragment<wmma::accumulator, 16, 16, 16, float> cfrag;
        wmma::fill_fragment(cfrag, 0.f);
#pragma unroll
        for (int k = 0; k < 8; k++) {
            wmma::fragment<wmma::matrix_a, 16, 16, 16, __half, wmma::row_major> a;
            wmma::fragment<wmma::matrix_b, 16, 16, 16, __half, wmma::row_major> b;
            wmma::load_matrix_sync(a, xs + mt * 16 * 136 + k * 16, 136);
            wmma::load_matrix_sync(b, ws + k * 16 * 64 + warp * 16, 64);
            wmma::mma_sync(cfrag, a, b, cfrag);
        }
        wmma::store_matrix_sync(cs + mt * 16 * 68 + warp * 16, cfrag, 68,
                                wmma::mem_row_major);
    }
    __syncthreads();

    // fp16 store of xw (52 cols, pads zero)
    for (int i = t; i < 32 * 26; i += 128) {
        int n = i / 26, c2 = i - n * 26;
        float lo = (2 * c2     < HC) ? cs[n * 68 + 2 * c2]     : 0.f;
        float hi = (2 * c2 + 1 < HC) ? cs[n * 68 + 2 * c2 + 1] : 0.f;
        *(__half2*)(g_xwh + (size_t)(n0 + n) * HCW + 2 * c2) = __floats2half2_rn(lo, hi);
    }

    // attention dots: 160 jobs (32 nodes x 5 heads)
    for (int j = t; j < 160; j += 128) {
        int n = j / 5, h = j - 5 * n;
        const float* row = &cs[n * 68 + h * 10];
        float a = 0.f, d = 0.f;
#pragma unroll
        for (int c = 0; c < 10; c++) {
            a += row[c] * s_as[h * 10 + c];
            d += row[c] * s_ad[h * 10 + c];
        }
        g_asrc[(n0 + n) * 8 + h] = a;
        g_adst[(n0 + n) * 8 + h] = d;
    }
}

// ---------------- K2: degree count (int4, 4 edges/thread) --------------------
__global__ void k_count(const int* __restrict__ ei) {
    int t = blockIdx.x * blockDim.x + threadIdx.x;
    if (t >= E_EDGES / 4) return;
    int4 d = __ldg((const int4*)(ei + E_EDGES) + t);
    atomicAdd(&g_deg[d.x], 1);
    atomicAdd(&g_deg[d.y], 1);
    atomicAdd(&g_deg[d.z], 1);
    atomicAdd(&g_deg[d.w], 1);
}

// ---------------- K3: two-level scan (3 cheap launches — measured 5.7us) -----
__global__ __launch_bounds__(NCHUNK) void k_scan1() {
    __shared__ int s[NCHUNK];
    int tid = threadIdx.x;
    int i = blockIdx.x * NCHUNK + tid;
    int v = (i < N_NODES) ? g_deg[i] : 0;
    s[tid] = v;
    __syncthreads();
    for (int off = 1; off < NCHUNK; off <<= 1) {
        int tv = (tid >= off) ? s[tid - off] : 0;
        __syncthreads();
        s[tid] += tv;
        __syncthreads();
    }
    if (i < N_NODES) g_offl[i] = s[tid] - v;
    if (tid == NCHUNK - 1) g_bsum[blockIdx.x] = s[tid];
}

__global__ __launch_bounds__(128) void k_scan2() {
    __shared__ int s[128];
    int tid = threadIdx.x;
    int v = (tid < NBLK_SCAN) ? g_bsum[tid] : 0;
    s[tid] = v;
    __syncthreads();
    for (int off = 1; off < 128; off <<= 1) {
        int tv = (tid >= off) ? s[tid - off] : 0;
        __syncthreads();
        s[tid] += tv;
        __syncthreads();
    }
    g_bpre[tid] = s[tid] - v;
}

__global__ __launch_bounds__(NCHUNK) void k_scan3() {
    int i = blockIdx.x * NCHUNK + threadIdx.x;
    if (i >= N_NODES) return;
    int st = g_offl[i] + g_bpre[i >> 10];
    g_start[i] = st;
    g_pos[i]   = st;
}

// ---------------- K4: fill CSR (int4, 4 edges/thread) ------------------------
__global__ void k_fill(const int* __restrict__ ei) {
    int t = blockIdx.x * blockDim.x + threadIdx.x;
    if (t >= E_EDGES / 4) return;
    int4 s4 = __ldg((const int4*)ei + t);
    int4 d4 = __ldg((const int4*)(ei + E_EDGES) + t);
    g_csrc[atomicAdd(&g_pos[d4.x], 1)] = s4.x;
    g_csrc[atomicAdd(&g_pos[d4.y], 1)] = s4.y;
    g_csrc[atomicAdd(&g_pos[d4.z], 1)] = s4.z;
    g_csrc[atomicAdd(&g_pos[d4.w], 1)] = s4.w;
}

// ---------------- K5: gather SpMM (16-lane groups, 2-deep prefetch) ----------
__device__ __forceinline__ float eluf(float v) { return v > 0.f ? v : expm1f(v); }

__global__ __launch_bounds__(512) void k_spmm(const float* __restrict__ bias,
                                              const int* __restrict__ batch) {
    __shared__ float4 red[32][13];
    __shared__ float  sb[HCW];
    __shared__ int    sgf, sgl;

    int tid = threadIdx.x;
    int n_local = tid >> 4;
    int lane = tid & 15;
    int n = blockIdx.x * 32 + n_local;             // N = 32*3125 exact

    if (tid < HC) sb[tid] = bias[tid];
    if (tid >= HC && tid < HCW) sb[tid] = 0.f;
    if (tid == 0)   sgf = __ldg(batch + blockIdx.x * 32);
    if (tid == 511) sgl = __ldg(batch + blockIdx.x * 32 + 31);

    int g = __ldg(batch + n);
    int start = g_start[n];
    int deg = g_deg[n];

    int q  = lane;                                  // quad id (valid < 13)
    int c0 = 4 * q;
    int hlo = min(c0 / 10, 4);
    int hhi = min((c0 + 3) / 10, 4);
    bool jlo1 = ((c0 + 1) / 10) == hlo || c0 + 1 >= HC;
    bool jlo2 = ((c0 + 2) / 10) == hlo || c0 + 2 >= HC;
    bool jlo3 = ((c0 + 3) / 10) == hlo || c0 + 3 >= HC;

    unsigned hm = 0xFFFFu << (tid & 16);            // half-warp mask

    float adv = 0.f;
    if (lane < NHEADS) adv = __ldg(g_adst + n * 8 + lane);

    float4 acc = make_float4(0.f, 0.f, 0.f, 0.f);
    float denlo = 0.f, denhi = 0.f;

    // edge stream: self-loop first, then deg CSR edges; src ids prefetched
    // two iterations ahead so the dependent asrc/xw gathers pipeline.
    int end = start + deg;
    int s_next  = n;                                           // consumed at i=start
    int s_next2 = (start < end) ? __ldg(g_csrc + start) : n;   // consumed at i=start+1
    for (int i = start; i <= end; ++i) {
        int s = s_next;
        s_next = s_next2;
        if (i + 1 < end) s_next2 = __ldg(g_csrc + i + 1);

        float w = 0.f;
        if (lane < NHEADS) {
            float l = __ldg(g_asrc + s * 8 + lane) + adv;
            l = l > 0.f ? l : NEG_SLOPE * l;
            w = __expf(l);
        }
        float wlo = __shfl_sync(hm, w, hlo, 16);
        float whi = __shfl_sync(hm, w, hhi, 16);

        if (lane < 13) {
            uint2 u = __ldg((const uint2*)(g_xwh + (size_t)s * HCW + c0));
            float2 f0 = __half22float2(*(__half2*)&u.x);
            float2 f1 = __half22float2(*(__half2*)&u.y);
            acc.x += wlo * f0.x;
            acc.y += (jlo1 ? wlo : whi) * f0.y;
            acc.z += (jlo2 ? wlo : whi) * f1.x;
            acc.w += (jlo3 ? wlo : whi) * f1.y;
        }
        denlo += wlo; denhi += whi;
    }

    __syncthreads();

    float4 o = make_float4(0.f, 0.f, 0.f, 0.f);
    if (lane < 13) {
        float ilo = 1.f / denlo, ihi = 1.f / denhi;
        o.x = eluf(acc.x * ilo + sb[c0 + 0]);
        o.y = eluf(acc.y * (jlo1 ? ilo : ihi) + sb[c0 + 1]);
        o.z = eluf(acc.z * (jlo2 ? ilo : ihi) + sb[c0 + 2]);
        o.w = eluf(acc.w * (jlo3 ? ilo : ihi) + sb[c0 + 3]);
        if (c0 + 2 >= HC) o.z = 0.f;
        if (c0 + 3 >= HC) o.w = 0.f;
        red[n_local][q] = o;
    }
    __syncthreads();

    if (sgf == sgl) {
#pragma unroll
        for (int sft = 16; sft > 0; sft >>= 1) {
            if (n_local < sft && lane < 13) {
                float4 a = red[n_local][lane];
                float4 b = red[n_local + sft][lane];
                a.x += b.x; a.y += b.y; a.z += b.z; a.w += b.w;
                red[n_local][lane] = a;
            }
            __syncthreads();
        }
        if (n_local == 0 && lane < 13) {
            float4 r = red[0][lane];
            red4(&g_gsum[sgf * HCW + 4 * lane], r.x, r.y, r.z, r.w);
        }
        if (tid == 0) red1(&g_cnt[sgf], 32.f);
    } else {
        if (lane < 13) red4(&g_gsum[g * HCW + c0], o.x, o.y, o.z, o.w);
        if (lane == 0) red1(&g_cnt[g], 1.f);
    }
}

// ---------------- K6: final linear + sigmoid --------------------------------
__global__ void k_final(const float* __restrict__ lin_w,
                        const float* __restrict__ lin_b,
                        float* __restrict__ out, int out_size) {
    int g = threadIdx.x;
    float cnt = g_cnt[g];
    float inv = 1.f / fmaxf(cnt, 1.f);
    float dot = 0.f;
#pragma unroll
    for (int c = 0; c < HC; c++) {
        float h = g_gsum[g * HCW + c] * inv;
        int idx = g * HC + c;
        if (idx < out_size) out[idx] = h;
        dot += h * __ldg(lin_w + c);
    }
    float y = 1.f / (1.f + __expf(-(dot + __ldg(lin_b))));
    int yidx = NGRAPH * HC + g;
    if (yidx < out_size) out[yidx] = y;
}

// ---------------- launch -----------------------------------------------------
extern "C" void kernel_launch(void* const* d_in, const int* in_sizes, int n_in,
                              void* d_out, int out_size) {
    const float* x       = (const float*)d_in[0];
    const float* W       = (const float*)d_in[1];
    const float* att_src = (const float*)d_in[2];
    const float* att_dst = (const float*)d_in[3];
    const float* bias    = (const float*)d_in[4];
    const float* lin_w   = (const float*)d_in[5];
    const float* lin_b   = (const float*)d_in[6];
    const int*   ei      = (const int*)d_in[7];
    const int*   batch   = (const int*)d_in[8];
    float*       out     = (float*)d_out;

    k_init <<<256, 256>>>();
    k_count<<<(E_EDGES / 4 + 255) / 256, 256>>>(ei);
    k_gemm <<<N_NODES / 32, 128>>>(x, W, att_src, att_dst);
    k_scan1<<<NBLK_SCAN, NCHUNK>>>();
    k_scan2<<<1, 128>>>();
    k_scan3<<<NBLK_SCAN, NCHUNK>>>();
    k_fill <<<(E_EDGES / 4 + 255) / 256, 256>>>(ei);
    k_spmm <<<N_NODES / 32, 512>>>(bias, batch);
    k_final<<<1, 256>>>(lin_w, lin_b, out, out_size);
}

// round 11
// speedup vs baseline: 1.1272x; 1.0013x over previous
#include <cuda_runtime.h>
#include <cuda_fp16.h>
#include <mma.h>
using namespace nvcuda;

#define N_NODES 100000
#define E_EDGES 1600000
#define DIM     128
#define HC      50          // H*C
#define HCW     52          // fp16 row length (26 half2, 13 x 8B)
#define NHEADS  5
#define NGRAPH  256
#define NEG_SLOPE 0.2f
#define NCHUNK  1024
#define NBLK_SCAN ((N_NODES + NCHUNK - 1) / NCHUNK)   // 98

// ---------------- scratch ----------------------------------------------------
__device__ __align__(16) __half g_xwh [N_NODES * HCW];  // fp16 projected feats
__device__ __align__(16) float g_asrc [N_NODES * 8];
__device__ __align__(16) float g_adst [N_NODES * 8];
__device__ __align__(16) float g_gsum [NGRAPH * HCW];
__device__ __align__(16) float g_cnt  [NGRAPH];
__device__ int g_deg   [N_NODES];
__device__ int g_offl  [N_NODES];
__device__ int g_bpre  [128];
__device__ int g_bsum  [128];
__device__ int g_start [N_NODES];
__device__ int g_pos   [N_NODES];
__device__ int g_csrc  [E_EDGES];

// ---------------- reductions -------------------------------------------------
__device__ __forceinline__ void red4(float* p, float a, float b, float c, float d) {
    asm volatile("red.global.add.v4.f32 [%0], {%1,%2,%3,%4};"
                 :: "l"(p), "f"(a), "f"(b), "f"(c), "f"(d) : "memory");
}
__device__ __forceinline__ void red1(float* p, float a) {
    asm volatile("red.global.add.f32 [%0], %1;" :: "l"(p), "f"(a) : "memory");
}

// ---------------- K0: init ---------------------------------------------------
__global__ void k_init() {
    int i = blockIdx.x * blockDim.x + threadIdx.x;
    int stride = gridDim.x * blockDim.x;
    for (int j = i; j < N_NODES; j += stride) g_deg[j] = 0;
    for (int j = i; j < NGRAPH * HCW; j += stride) g_gsum[j] = 0.f;
    for (int j = i; j < NGRAPH; j += stride) g_cnt[j] = 0.f;
}

// ---------------- K1: wmma GEMM + attention dots + fp16 store ----------------
__global__ __launch_bounds__(128) void k_gemm(const float* __restrict__ x,
                                              const float* __restrict__ W,
                                              const float* __restrict__ att_src,
                                              const float* __restrict__ att_dst) {
    __shared__ __half xs[32 * 136];
    __shared__ __half ws[128 * 64];
    __shared__ float  cs[32 * 68];
    __shared__ float  s_as[HC], s_ad[HC];

    int t = threadIdx.x, warp = t >> 5;
    int n0 = blockIdx.x * 32;

    if (t < HC) { s_as[t] = att_src[t]; s_ad[t] = att_dst[t]; }

    const float4* xg = (const float4*)(x + (size_t)n0 * DIM);
    for (int i = t; i < 32 * 32; i += 128) {
        int r = i >> 5, c4 = i & 31;
        float4 v = xg[r * 32 + c4];
        __half* p = &xs[r * 136 + c4 * 4];
        p[0] = __float2half(v.x); p[1] = __float2half(v.y);
        p[2] = __float2half(v.z); p[3] = __float2half(v.w);
    }
    for (int i = t; i < 128 * 64; i += 128) {
        int r = i >> 6, c = i & 63;
        ws[i] = __float2half(c < HC ? W[r * HC + c] : 0.f);
    }
    __syncthreads();

#pragma unroll
    for (int mt = 0; mt < 2; mt++) {
        wmma::fragment<wmma::accumulator, 16, 16, 16, float> cfrag;
        wmma::fill_fragment(cfrag, 0.f);
#pragma unroll
        for (int k = 0; k < 8; k++) {
            wmma::fragment<wmma::matrix_a, 16, 16, 16, __half, wmma::row_major> a;
            wmma::fragment<wmma::matrix_b, 16, 16, 16, __half, wmma::row_major> b;
            wmma::load_matrix_sync(a, xs + mt * 16 * 136 + k * 16, 136);
            wmma::load_matrix_sync(b, ws + k * 16 * 64 + warp * 16, 64);
            wmma::mma_sync(cfrag, a, b, cfrag);
        }
        wmma::store_matrix_sync(cs + mt * 16 * 68 + warp * 16, cfrag, 68,
                                wmma::mem_row_major);
    }
    __syncthreads();

    // fp16 store of xw (52 cols, pads zero)
    for (int i = t; i < 32 * 26; i += 128) {
        int n = i / 26, c2 = i - n * 26;
        float lo = (2 * c2     < HC) ? cs[n * 68 + 2 * c2]     : 0.f;
        float hi = (2 * c2 + 1 < HC) ? cs[n * 68 + 2 * c2 + 1] : 0.f;
        *(__half2*)(g_xwh + (size_t)(n0 + n) * HCW + 2 * c2) = __floats2half2_rn(lo, hi);
    }

    // attention dots: 160 jobs (32 nodes x 5 heads)
    for (int j = t; j < 160; j += 128) {
        int n = j / 5, h = j - 5 * n;
        const float* row = &cs[n * 68 + h * 10];
        float a = 0.f, d = 0.f;
#pragma unroll
        for (int c = 0; c < 10; c++) {
            a += row[c] * s_as[h * 10 + c];
            d += row[c] * s_ad[h * 10 + c];
        }
        g_asrc[(n0 + n) * 8 + h] = a;
        g_adst[(n0 + n) * 8 + h] = d;
    }
}

// ---------------- K2: degree count (int4, 4 edges/thread) --------------------
__global__ void k_count(const int* __restrict__ ei) {
    int t = blockIdx.x * blockDim.x + threadIdx.x;
    if (t >= E_EDGES / 4) return;
    int4 d = __ldg((const int4*)(ei + E_EDGES) + t);
    atomicAdd(&g_deg[d.x], 1);
    atomicAdd(&g_deg[d.y], 1);
    atomicAdd(&g_deg[d.z], 1);
    atomicAdd(&g_deg[d.w], 1);
}

// ---------------- K3: two-level scan (3 cheap launches — measured 5.7us) -----
__global__ __launch_bounds__(NCHUNK) void k_scan1() {
    __shared__ int s[NCHUNK];
    int tid = threadIdx.x;
    int i = blockIdx.x * NCHUNK + tid;
    int v = (i < N_NODES) ? g_deg[i] : 0;
    s[tid] = v;
    __syncthreads();
    for (int off = 1; off < NCHUNK; off <<= 1) {
        int tv = (tid >= off) ? s[tid - off] : 0;
        __syncthreads();
        s[tid] += tv;
        __syncthreads();
    }
    if (i < N_NODES) g_offl[i] = s[tid] - v;
    if (tid == NCHUNK - 1) g_bsum[blockIdx.x] = s[tid];
}

__global__ __launch_bounds__(128) void k_scan2() {
    __shared__ int s[128];
    int tid = threadIdx.x;
    int v = (tid < NBLK_SCAN) ? g_bsum[tid] : 0;
    s[tid] = v;
    __syncthreads();
    for (int off = 1; off < 128; off <<= 1) {
        int tv = (tid >= off) ? s[tid - off] : 0;
        __syncthreads();
        s[tid] += tv;
        __syncthreads();
    }
    g_bpre[tid] = s[tid] - v;
}

__global__ __launch_bounds__(NCHUNK) void k_scan3() {
    int i = blockIdx.x * NCHUNK + threadIdx.x;
    if (i >= N_NODES) return;
    int st = g_offl[i] + g_bpre[i >> 10];
    g_start[i] = st;
    g_pos[i]   = st;
}

// ---------------- K4: fill CSR (int4, 4 edges/thread) ------------------------
__global__ void k_fill(const int* __restrict__ ei) {
    int t = blockIdx.x * blockDim.x + threadIdx.x;
    if (t >= E_EDGES / 4) return;
    int4 s4 = __ldg((const int4*)ei + t);
    int4 d4 = __ldg((const int4*)(ei + E_EDGES) + t);
    g_csrc[atomicAdd(&g_pos[d4.x], 1)] = s4.x;
    g_csrc[atomicAdd(&g_pos[d4.y], 1)] = s4.y;
    g_csrc[atomicAdd(&g_pos[d4.z], 1)] = s4.z;
    g_csrc[atomicAdd(&g_pos[d4.w], 1)] = s4.w;
}

// ---------------- K5: gather SpMM (16-lane groups, 2-deep prefetch) ----------
__device__ __forceinline__ float eluf(float v) { return v > 0.f ? v : expm1f(v); }

__global__ __launch_bounds__(512) void k_spmm(const float* __restrict__ bias,
                                              const int* __restrict__ batch) {
    __shared__ float4 red[32][13];
    __shared__ float  sb[HCW];
    __shared__ int    sgf, sgl;

    int tid = threadIdx.x;
    int n_local = tid >> 4;
    int lane = tid & 15;
    int n = blockIdx.x * 32 + n_local;             // N = 32*3125 exact

    if (tid < HC) sb[tid] = bias[tid];
    if (tid >= HC && tid < HCW) sb[tid] = 0.f;
    if (tid == 0)   sgf = __ldg(batch + blockIdx.x * 32);
    if (tid == 511) sgl = __ldg(batch + blockIdx.x * 32 + 31);

    int g = __ldg(batch + n);
    int start = g_start[n];
    int deg = g_deg[n];

    int q  = lane;                                  // quad id (valid < 13)
    int c0 = 4 * q;
    int hlo = min(c0 / 10, 4);
    int hhi = min((c0 + 3) / 10, 4);
    bool jlo1 = ((c0 + 1) / 10) == hlo || c0 + 1 >= HC;
    bool jlo2 = ((c0 + 2) / 10) == hlo || c0 + 2 >= HC;
    bool jlo3 = ((c0 + 3) / 10) == hlo || c0 + 3 >= HC;

    unsigned hm = 0xFFFFu << (tid & 16);            // half-warp mask

    float adv = 0.f;
    if (lane < NHEADS) adv = __ldg(g_adst + n * 8 + lane);

    float4 acc = make_float4(0.f, 0.f, 0.f, 0.f);
    float denlo = 0.f, denhi = 0.f;

    // edge stream: self-loop first, then deg CSR edges; src ids prefetched
    // two iterations ahead so the dependent asrc/xw gathers pipeline.
    int end = start + deg;
    int s_next  = n;                                           // consumed at i=start
    int s_next2 = (start < end) ? __ldg(g_csrc + start) : n;   // consumed at i=start+1
    for (int i = start; i <= end; ++i) {
        int s = s_next;
        s_next = s_next2;
        if (i + 1 < end) s_next2 = __ldg(g_csrc + i + 1);

        float w = 0.f;
        if (lane < NHEADS) {
            float l = __ldg(g_asrc + s * 8 + lane) + adv;
            l = l > 0.f ? l : NEG_SLOPE * l;
            w = __expf(l);
        }
        float wlo = __shfl_sync(hm, w, hlo, 16);
        float whi = __shfl_sync(hm, w, hhi, 16);

        if (lane < 13) {
            uint2 u = __ldg((const uint2*)(g_xwh + (size_t)s * HCW + c0));
            float2 f0 = __half22float2(*(__half2*)&u.x);
            float2 f1 = __half22float2(*(__half2*)&u.y);
            acc.x += wlo * f0.x;
            acc.y += (jlo1 ? wlo : whi) * f0.y;
            acc.z += (jlo2 ? wlo : whi) * f1.x;
            acc.w += (jlo3 ? wlo : whi) * f1.y;
        }
        denlo += wlo; denhi += whi;
    }

    __syncthreads();

    float4 o = make_float4(0.f, 0.f, 0.f, 0.f);
    if (lane < 13) {
        float ilo = 1.f / denlo, ihi = 1.f / denhi;
        o.x = eluf(acc.x * ilo + sb[c0 + 0]);
        o.y = eluf(acc.y * (jlo1 ? ilo : ihi) + sb[c0 + 1]);
        o.z = eluf(acc.z * (jlo2 ? ilo : ihi) + sb[c0 + 2]);
        o.w = eluf(acc.w * (jlo3 ? ilo : ihi) + sb[c0 + 3]);
        if (c0 + 2 >= HC) o.z = 0.f;
        if (c0 + 3 >= HC) o.w = 0.f;
        red[n_local][q] = o;
    }
    __syncthreads();

    if (sgf == sgl) {
#pragma unroll
        for (int sft = 16; sft > 0; sft >>= 1) {
            if (n_local < sft && lane < 13) {
                float4 a = red[n_local][lane];
                float4 b = red[n_local + sft][lane];
                a.x += b.x; a.y += b.y; a.z += b.z; a.w += b.w;
                red[n_local][lane] = a;
            }
            __syncthreads();
        }
        if (n_local == 0 && lane < 13) {
            float4 r = red[0][lane];
            red4(&g_gsum[sgf * HCW + 4 * lane], r.x, r.y, r.z, r.w);
        }
        if (tid == 0) red1(&g_cnt[sgf], 32.f);
    } else {
        if (lane < 13) red4(&g_gsum[g * HCW + c0], o.x, o.y, o.z, o.w);
        if (lane == 0) red1(&g_cnt[g], 1.f);
    }
}

// ---------------- K6: final linear + sigmoid --------------------------------
__global__ void k_final(const float* __restrict__ lin_w,
                        const float* __restrict__ lin_b,
                        float* __restrict__ out, int out_size) {
    int g = threadIdx.x;
    float cnt = g_cnt[g];
    float inv = 1.f / fmaxf(cnt, 1.f);
    float dot = 0.f;
#pragma unroll
    for (int c = 0; c < HC; c++) {
        float h = g_gsum[g * HCW + c] * inv;
        int idx = g * HC + c;
        if (idx < out_size) out[idx] = h;
        dot += h * __ldg(lin_w + c);
    }
    float y = 1.f / (1.f + __expf(-(dot + __ldg(lin_b))));
    int yidx = NGRAPH * HC + g;
    if (yidx < out_size) out[yidx] = y;
}

// ---------------- launch -----------------------------------------------------
extern "C" void kernel_launch(void* const* d_in, const int* in_sizes, int n_in,
                              void* d_out, int out_size) {
    const float* x       = (const float*)d_in[0];
    const float* W       = (const float*)d_in[1];
    const float* att_src = (const float*)d_in[2];
    const float* att_dst = (const float*)d_in[3];
    const float* bias    = (const float*)d_in[4];
    const float* lin_w   = (const float*)d_in[5];
    const float* lin_b   = (const float*)d_in[6];
    const int*   ei      = (const int*)d_in[7];
    const int*   batch   = (const int*)d_in[8];
    float*       out     = (float*)d_out;

    k_init <<<256, 256>>>();
    k_count<<<(E_EDGES / 4 + 255) / 256, 256>>>(ei);
    k_gemm <<<N_NODES / 32, 128>>>(x, W, att_src, att_dst);
    k_scan1<<<NBLK_SCAN, NCHUNK>>>();
    k_scan2<<<1, 128>>>();
    k_scan3<<<NBLK_SCAN, NCHUNK>>>();
    k_fill <<<(E_EDGES / 4 + 255) / 256, 256>>>(ei);
    k_spmm <<<N_NODES / 32, 512>>>(bias, batch);
    k_final<<<1, 256>>>(lin_w, lin_b, out, out_size);
}